// round 10
// baseline (speedup 1.0000x reference)
#include <cuda_runtime.h>
#include <math.h>
#include <stdint.h>

#define CB   4
#define CS   2048
#define CD   1024
#define CH   16
#define CDH  64
#define MROWS (CB*CS)
#define LN_EPS 1e-5f

// ---------------- scratch ----------------
__device__ float g_chunk[(size_t)MROWS*CD];
__device__ float g_qkv  [(size_t)MROWS*3*CD];
__device__ float g_attn [(size_t)MROWS*CD];
__device__ float g_proj [(size_t)MROWS*CD];

// ---------------- helpers ----------------
__device__ __forceinline__ uint32_t f2tf(float x) {
    uint32_t u; asm("cvt.rna.tf32.f32 %0, %1;" : "=r"(u) : "f"(x)); return u;
}
__device__ __forceinline__ float tfbits(float x) {
    return __uint_as_float(f2tf(x));
}
__device__ __forceinline__ float ex2f(float x) {
    float y; asm("ex2.approx.f32 %0, %1;" : "=f"(y) : "f"(x)); return y;
}
__device__ __forceinline__ uint32_t pack_bf16(float lo, float hi) {
    uint32_t r; asm("cvt.rn.bf16x2.f32 %0, %1, %2;" : "=r"(r) : "f"(hi), "f"(lo));
    return r;
}
__device__ __forceinline__ void mma_tf32(float c[4], const uint32_t a[4],
                                         const uint32_t b[2]) {
    asm volatile(
        "mma.sync.aligned.m16n8k8.row.col.f32.tf32.tf32.f32 "
        "{%0,%1,%2,%3}, {%4,%5,%6,%7}, {%8,%9}, {%0,%1,%2,%3};\n"
        : "+f"(c[0]), "+f"(c[1]), "+f"(c[2]), "+f"(c[3])
        : "r"(a[0]), "r"(a[1]), "r"(a[2]), "r"(a[3]), "r"(b[0]), "r"(b[1]));
}
__device__ __forceinline__ void mma_bf16(float c[4], const uint32_t a[4],
                                         const uint32_t b[2]) {
    asm volatile(
        "mma.sync.aligned.m16n8k16.row.col.f32.bf16.bf16.f32 "
        "{%0,%1,%2,%3}, {%4,%5,%6,%7}, {%8,%9}, {%0,%1,%2,%3};\n"
        : "+f"(c[0]), "+f"(c[1]), "+f"(c[2]), "+f"(c[3])
        : "r"(a[0]), "r"(a[1]), "r"(a[2]), "r"(a[3]), "r"(b[0]), "r"(b[1]));
}
__device__ __forceinline__ void ldsm_x4(uint32_t& r0, uint32_t& r1,
                                        uint32_t& r2, uint32_t& r3,
                                        uint32_t addr) {
    asm volatile("ldmatrix.sync.aligned.m8n8.x4.shared.b16 {%0,%1,%2,%3}, [%4];\n"
                 : "=r"(r0), "=r"(r1), "=r"(r2), "=r"(r3) : "r"(addr));
}
__device__ __forceinline__ void ldsm_x4_t(uint32_t& r0, uint32_t& r1,
                                          uint32_t& r2, uint32_t& r3,
                                          uint32_t addr) {
    asm volatile("ldmatrix.sync.aligned.m8n8.x4.trans.shared.b16 {%0,%1,%2,%3}, [%4];\n"
                 : "=r"(r0), "=r"(r1), "=r"(r2), "=r"(r3) : "r"(addr));
}
__device__ __forceinline__ uint32_t smem_u32(const void* p) {
    return (uint32_t)__cvta_generic_to_shared(p);
}
__device__ __forceinline__ void cp16(uint32_t dst, const void* src) {
    asm volatile("cp.async.cg.shared.global [%0], [%1], 16;\n"
                 :: "r"(dst), "l"(src));
}
__device__ __forceinline__ void cp16z(uint32_t dst, const void* src, int srcsz) {
    asm volatile("cp.async.cg.shared.global [%0], [%1], 16, %2;\n"
                 :: "r"(dst), "l"(src), "r"(srcsz));
}
__device__ __forceinline__ void cp_commit() {
    asm volatile("cp.async.commit_group;\n");
}
template<int N> __device__ __forceinline__ void cp_wait() {
    asm volatile("cp.async.wait_group %0;\n" :: "n"(N));
}

// ---------------------------------------------------------------------------
// TF32 NT GEMM (exact R8): 3-stage cp.async, one sync/iter, LDSM fragments.
// ---------------------------------------------------------------------------
#define GSTG (128 * 36)
#define GK_SMEM (3 * 2 * GSTG * 4)   // 110592 B

template<bool WINDOW>
__global__ __launch_bounds__(256, 2)
void gemm_tf32(const float* __restrict__ A, const float* __restrict__ B,
               const float* __restrict__ bias, float* __restrict__ C,
               int M, int N, int K) {
    extern __shared__ float sm[];
    float* As = sm;               // [3][128][36]
    float* Bs = sm + 3 * GSTG;    // [3][128][36]

    int tid = threadIdx.x;
    int bm = blockIdx.y * 128, bn = blockIdx.x * 128;
    int warp = tid >> 5, lane = tid & 31, gid = lane >> 2, tig = lane & 3;
    int l7 = lane & 7, l3 = lane >> 3;
    int wm = (warp >> 2) * 64, wn = (warp & 3) * 32;

    float acc[4][4][4];
#pragma unroll
    for (int i = 0; i < 4; i++)
#pragma unroll
        for (int j = 0; j < 4; j++)
#pragma unroll
            for (int c = 0; c < 4; c++) acc[i][j][c] = 0.f;

    auto load_stage = [&](int st, int k0) {
#pragma unroll
        for (int p = 0; p < 4; p++) {
            int id  = tid + p * 256;
            int row = id >> 3;
            int kq  = (id & 7) << 2;
            uint32_t da = smem_u32(&As[st * GSTG + row * 36 + kq]);
            if (WINDOW) {
                int m = bm + row;
                int bidx = m >> 11, s = m & (CS - 1);
                int f = k0 + kq, kk = f >> 10, j = f & (CD - 1);
                const float* src = A + (((size_t)bidx * CS + s + kk) << 10) + j;
                cp16z(da, src, (s + kk < CS) ? 16 : 0);
            } else {
                cp16(da, A + (size_t)(bm + row) * K + k0 + kq);
            }
            cp16(smem_u32(&Bs[st * GSTG + row * 36 + kq]),
                 B + (size_t)(bn + row) * K + k0 + kq);
        }
        cp_commit();
    };

    int nk = K >> 5;
    load_stage(0, 0);
    load_stage(1, 32);

    int st = 0;
    int pfst = 2;
    for (int kc = 0; kc < nk; kc++) {
        cp_wait<1>();
        __syncthreads();

        int pf = kc + 2;
        if (pf < nk) load_stage(pfst, pf << 5);
        else cp_commit();

        uint32_t Abase = smem_u32(As + st * GSTG);
        uint32_t Bbase = smem_u32(Bs + st * GSTG);
#pragma unroll
        for (int g = 0; g < 32; g += 8) {
            uint32_t a[4][4], bf[4][2];
#pragma unroll
            for (int ti = 0; ti < 4; ti++) {
                int m0 = wm + ti * 16;
                uint32_t adr = Abase +
                    ((m0 + (l3 & 1) * 8 + l7) * 36 + g + (l3 >> 1) * 4) * 4;
                ldsm_x4(a[ti][0], a[ti][1], a[ti][2], a[ti][3], adr);
            }
#pragma unroll
            for (int tp = 0; tp < 2; tp++) {
                int n0 = wn + tp * 16;
                uint32_t adr = Bbase +
                    ((n0 + (l3 >> 1) * 8 + l7) * 36 + g + (l3 & 1) * 4) * 4;
                ldsm_x4(bf[2 * tp][0], bf[2 * tp][1],
                        bf[2 * tp + 1][0], bf[2 * tp + 1][1], adr);
            }
#pragma unroll
            for (int ti = 0; ti < 4; ti++)
#pragma unroll
                for (int tj = 0; tj < 4; tj++)
                    mma_tf32(acc[ti][tj], a[ti], bf[tj]);
        }

        st   = (st   == 2) ? 0 : st + 1;
        pfst = (pfst == 2) ? 0 : pfst + 1;
    }

#pragma unroll
    for (int ti = 0; ti < 4; ti++) {
#pragma unroll
        for (int hh = 0; hh < 2; hh++) {
            int row = bm + wm + ti * 16 + gid + 8 * hh;
#pragma unroll
            for (int tj = 0; tj < 4; tj++) {
                int col = bn + wn + tj * 8 + 2 * tig;
                float2 o;
                o.x = acc[ti][tj][2 * hh + 0] + bias[col + 0];
                o.y = acc[ti][tj][2 * hh + 1] + bias[col + 1];
                *(float2*)&C[(size_t)row * N + col] = o;
            }
        }
    }
}

// ---------------------------------------------------------------------------
// Flash attention, mi=2: 8 warps x 32 q-rows = 256-row q-tile, 1 CTA/SM.
// K/V fragments loaded once per warp feed BOTH mi sub-tiles (halves smem
// crossbar traffic per q-row vs R8). kv tiles of 64, cp.async 2-stage.
// ---------------------------------------------------------------------------
#define FA_KV  (64 * 68)
#define FA_SMEM ((4 * FA_KV) * 4 + 2 * 64 * 36 * 4)   // 88064 B

__global__ __launch_bounds__(256, 1)
void flash_tf32(const float* __restrict__ qkv, float* __restrict__ out) {
    extern __shared__ float sm[];
    float*    Ks   = sm;                      // [2][64][68] f32
    float*    Vraw = sm + 2 * FA_KV;          // [2][64][68] f32
    uint32_t* Vbf  = (uint32_t*)(sm + 4 * FA_KV);  // [2][64][36] bf16x2

    int b = blockIdx.y >> 4, h = blockIdx.y & 15;
    int q0 = blockIdx.x << 8;                 // 256-row q tiles
    int tid = threadIdx.x, warp = tid >> 5, lane = tid & 31;
    int gid = lane >> 2, tig = lane & 3;
    int wq = warp * 32;
    int l7 = lane & 7, l3 = lane >> 3;

    const size_t rstr = 3 * CD;
    const float* qb = qkv + (size_t)b * CS * rstr + h * CDH;
    const float* kb = qb + CD;
    const float* vb = qb + 2 * CD;
    const float qscale = 1.4426950408889634f * 0.125f;   // log2e / sqrt(dh)

    // ---- stage Q in two 128-row passes through the K double-buffer
    float* Qt = Ks;   // [128][68]
    uint32_t qf[2][8][4];
#pragma unroll
    for (int pass = 0; pass < 2; pass++) {
#pragma unroll
        for (int p = 0; p < 8; p++) {
            int id  = tid + p * 256;
            int row = id >> 4;
            int c4  = (id & 15) << 2;
            float4 v = *(const float4*)
                &qb[(size_t)(q0 + pass * 128 + row) * rstr + c4];
            Qt[row * 68 + c4 + 0] = tfbits(v.x * qscale);
            Qt[row * 68 + c4 + 1] = tfbits(v.y * qscale);
            Qt[row * 68 + c4 + 2] = tfbits(v.z * qscale);
            Qt[row * 68 + c4 + 3] = tfbits(v.w * qscale);
        }
        __syncthreads();
        if ((warp >> 2) == pass) {
            int lb = (warp & 3) * 32;
#pragma unroll
            for (int mi = 0; mi < 2; mi++) {
                int r0 = lb + mi * 16 + gid;
#pragma unroll
                for (int g = 0; g < 8; g++) {
                    qf[mi][g][0] = __float_as_uint(Qt[r0 * 68 + g * 8 + tig]);
                    qf[mi][g][1] = __float_as_uint(Qt[(r0 + 8) * 68 + g * 8 + tig]);
                    qf[mi][g][2] = __float_as_uint(Qt[r0 * 68 + g * 8 + tig + 4]);
                    qf[mi][g][3] = __float_as_uint(Qt[(r0 + 8) * 68 + g * 8 + tig + 4]);
                }
            }
        }
        __syncthreads();
    }

    auto load_kv = [&](int st, int kt) {
#pragma unroll
        for (int p = 0; p < 4; p++) {
            int id  = tid + p * 256;
            int row = id >> 4;
            int c4  = (id & 15) << 2;
            cp16(smem_u32(&Ks[st * FA_KV + row * 68 + c4]),
                 kb + (size_t)(kt + row) * rstr + c4);
            cp16(smem_u32(&Vraw[st * FA_KV + row * 68 + c4]),
                 vb + (size_t)(kt + row) * rstr + c4);
        }
        cp_commit();
    };

    load_kv(0, 0);
    load_kv(1, 64);

    // O accumulators: per mi, 8 d-tiles + 1 ones (row-sum) tile
    float o[2][9][4];
#pragma unroll
    for (int mi = 0; mi < 2; mi++)
#pragma unroll
        for (int n = 0; n < 9; n++)
#pragma unroll
            for (int c = 0; c < 4; c++) o[mi][n][c] = 0.f;

    const uint32_t bones = (gid == 0) ? 0x3F803F80u : 0u;
    const int nkt = CS / 64;   // 32

    for (int it = 0; it < nkt; it++) {
        int st = it & 1;
        cp_wait<1>();
        __syncthreads();
        uint32_t Kbase = smem_u32(Ks + st * FA_KV);
        const float* Vr = Vraw + st * FA_KV;
        uint32_t* Vw = Vbf + st * 64 * 36;
        uint32_t Vbase = smem_u32(Vw);

        // V convert: raw f32 -> dedicated bf16 buffer
#pragma unroll
        for (int p = 0; p < 4; p++) {
            int id  = tid + p * 256;
            int row = id >> 4;
            int c4  = (id & 15) << 2;
            float4 v = *(const float4*)&Vr[row * 68 + c4];
            uint2 w;
            w.x = pack_bf16(v.x, v.y);
            w.y = pack_bf16(v.z, v.w);
            *(uint2*)&Vw[row * 36 + (c4 >> 1)] = w;
        }

        // S = Q @ K^T per n-pair; K fragments shared across both mi
        uint32_t pf[2][4][4];
#pragma unroll
        for (int np = 0; np < 4; np++) {
            float sc[2][2][4];   // [mi][nn][4], depth-8 chains, 4-way ILP
#pragma unroll
            for (int mi = 0; mi < 2; mi++)
#pragma unroll
                for (int nn = 0; nn < 2; nn++)
#pragma unroll
                    for (int c = 0; c < 4; c++) sc[mi][nn][c] = 0.f;
#pragma unroll
            for (int j = 0; j < 4; j++) {
#pragma unroll
                for (int nn = 0; nn < 2; nn++) {
                    uint32_t adr = Kbase +
                        ((np * 16 + nn * 8 + l7) * 68 + l3 * 4) * 4 + j * 64;
                    uint32_t k0, k1, k2, k3;
                    ldsm_x4(k0, k1, k2, k3, adr);
                    uint32_t b0[2] = {k0, k1};
                    uint32_t b1[2] = {k2, k3};
                    mma_tf32(sc[0][nn], qf[0][2 * j], b0);
                    mma_tf32(sc[0][nn], qf[0][2 * j + 1], b1);
                    mma_tf32(sc[1][nn], qf[1][2 * j], b0);
                    mma_tf32(sc[1][nn], qf[1][2 * j + 1], b1);
                }
            }
#pragma unroll
            for (int mi = 0; mi < 2; mi++)
#pragma unroll
                for (int nn = 0; nn < 2; nn++) {
                    pf[mi][np][nn * 2 + 0] =
                        pack_bf16(ex2f(sc[mi][nn][0]), ex2f(sc[mi][nn][1]));
                    pf[mi][np][nn * 2 + 1] =
                        pack_bf16(ex2f(sc[mi][nn][2]), ex2f(sc[mi][nn][3]));
                }
        }

        __syncthreads();   // Vbf visible; K[st]/Vraw[st] fully consumed

        if (it + 2 < nkt) load_kv(st, (it + 2) * 64);
        else cp_commit();

        // O += P @ V; V fragments shared across both mi
#pragma unroll
        for (int t = 0; t < 4; t++) {
#pragma unroll
            for (int a = 0; a < 4; a++) {
                uint32_t adr = Vbase +
                    (16 * t + (l3 & 1) * 8 + l7) * 144 +
                    (2 * a + (l3 >> 1)) * 16;
                uint32_t v0, v1, v2, v3;
                ldsm_x4_t(v0, v1, v2, v3, adr);
                uint32_t bv0[2] = {v0, v1};
                uint32_t bv1[2] = {v2, v3};
                mma_bf16(o[0][2 * a],     pf[0][t], bv0);
                mma_bf16(o[0][2 * a + 1], pf[0][t], bv1);
                mma_bf16(o[1][2 * a],     pf[1][t], bv0);
                mma_bf16(o[1][2 * a + 1], pf[1][t], bv1);
            }
            {
                uint32_t bv[2] = {bones, bones};
                mma_bf16(o[0][8], pf[0][t], bv);
                mma_bf16(o[1][8], pf[1][t], bv);
            }
        }
    }

    // normalize + write (row sums in tig==0 lanes of o[mi][8])
    int base = lane & 28;
#pragma unroll
    for (int mi = 0; mi < 2; mi++)
#pragma unroll
        for (int hh = 0; hh < 2; hh++) {
            float lsv = __shfl_sync(0xffffffffu, o[mi][8][hh ? 2 : 0], base);
            float inv = 1.f / lsv;
            int row = q0 + wq + mi * 16 + gid + 8 * hh;
#pragma unroll
            for (int n = 0; n < 8; n++) {
                int col = h * CDH + n * 8 + 2 * tig;
                float2 ov = make_float2(o[mi][n][2 * hh] * inv,
                                        o[mi][n][2 * hh + 1] * inv);
                *(float2*)&out[((size_t)b * CS + row) * CD + col] = ov;
            }
        }
}

// ---------------------------------------------------------------------------
// Fused residual add + LayerNorm
// ---------------------------------------------------------------------------
__global__ __launch_bounds__(256)
void add_ln(const float* __restrict__ chunk, const float* __restrict__ proj,
            const float* __restrict__ g, const float* __restrict__ beta,
            float* __restrict__ out) {
    int row = blockIdx.x;
    int tid = threadIdx.x;
    size_t base = (size_t)row * CD + tid * 4;

    float4 c = *(const float4*)&chunk[base];
    float4 p = *(const float4*)&proj[base];
    float4 x = make_float4(c.x + p.x, c.y + p.y, c.z + p.z, c.w + p.w);

    float s  = x.x + x.y + x.z + x.w;
    float s2 = x.x * x.x + x.y * x.y + x.z * x.z + x.w * x.w;
#pragma unroll
    for (int off = 16; off; off >>= 1) {
        s  += __shfl_xor_sync(0xffffffffu, s,  off);
        s2 += __shfl_xor_sync(0xffffffffu, s2, off);
    }
    __shared__ float rs[8], rs2[8];
    __shared__ float s_mu, s_rstd;
    int lane = tid & 31, warp = tid >> 5;
    if (lane == 0) { rs[warp] = s; rs2[warp] = s2; }
    __syncthreads();
    if (tid == 0) {
        float a = 0.f, b2 = 0.f;
#pragma unroll
        for (int w = 0; w < 8; w++) { a += rs[w]; b2 += rs2[w]; }
        float mean = a * (1.f / CD);
        float var  = b2 * (1.f / CD) - mean * mean;
        s_mu = mean;
        s_rstd = rsqrtf(var + LN_EPS);
    }
    __syncthreads();
    float mu = s_mu, rstd = s_rstd;

    float4 gv = *(const float4*)&g[tid * 4];
    float4 bv = *(const float4*)&beta[tid * 4];
    float4 y;
    y.x = (x.x - mu) * rstd * gv.x + bv.x;
    y.y = (x.y - mu) * rstd * gv.y + bv.y;
    y.z = (x.z - mu) * rstd * gv.z + bv.z;
    y.w = (x.w - mu) * rstd * gv.w + bv.w;
    *(float4*)&out[base] = y;
}

// ---------------------------------------------------------------------------
extern "C" void kernel_launch(void* const* d_in, const int* in_sizes, int n_in,
                              void* d_out, int out_size) {
    const float* emb     = (const float*)d_in[0];
    const float* chunk_w = (const float*)d_in[1];
    const float* chunk_b = (const float*)d_in[2];
    const float* in_w    = (const float*)d_in[3];
    const float* in_b    = (const float*)d_in[4];
    const float* out_w   = (const float*)d_in[5];
    const float* out_b   = (const float*)d_in[6];
    const float* ln_g    = (const float*)d_in[7];
    const float* ln_b    = (const float*)d_in[8];
    float* out = (float*)d_out;

    float *chunk, *qkv, *attn, *proj;
    cudaGetSymbolAddress((void**)&chunk, g_chunk);
    cudaGetSymbolAddress((void**)&qkv,   g_qkv);
    cudaGetSymbolAddress((void**)&attn,  g_attn);
    cudaGetSymbolAddress((void**)&proj,  g_proj);

    cudaFuncSetAttribute(gemm_tf32<true>,
                         cudaFuncAttributeMaxDynamicSharedMemorySize, GK_SMEM);
    cudaFuncSetAttribute(gemm_tf32<false>,
                         cudaFuncAttributeMaxDynamicSharedMemorySize, GK_SMEM);
    cudaFuncSetAttribute(flash_tf32,
                         cudaFuncAttributeMaxDynamicSharedMemorySize, FA_SMEM);

    // 1) chunk = windows @ chunk_w^T + chunk_b
    {
        dim3 grid(CD / 128, MROWS / 128);
        gemm_tf32<true><<<grid, 256, GK_SMEM>>>(emb, chunk_w, chunk_b, chunk,
                                                MROWS, CD, 2 * CD);
    }
    // 2) qkv = chunk @ in_proj_w^T + in_proj_b
    {
        dim3 grid(3 * CD / 128, MROWS / 128);
        gemm_tf32<false><<<grid, 256, GK_SMEM>>>(chunk, in_w, in_b, qkv,
                                                 MROWS, 3 * CD, CD);
    }
    // 3) flash attention (256-row q tiles)
    {
        dim3 grid(CS / 256, CB * CH);
        flash_tf32<<<grid, 256, FA_SMEM>>>(qkv, attn);
    }
    // 4) proj = attn @ out_proj_w^T + out_proj_b
    {
        dim3 grid(CD / 128, MROWS / 128);
        gemm_tf32<false><<<grid, 256, GK_SMEM>>>(attn, out_w, out_b, proj,
                                                 MROWS, CD, CD);
    }
    // 5) out = LayerNorm(chunk + proj)
    add_ln<<<MROWS, 256>>>(chunk, proj, ln_g, ln_b, out);
}

// round 11
// speedup vs baseline: 1.4706x; 1.4706x over previous
#include <cuda_runtime.h>
#include <cuda_fp16.h>
#include <math.h>
#include <stdint.h>

#define CB   4
#define CS   2048
#define CD   1024
#define CH   16
#define CDH  64
#define MROWS (CB*CS)
#define LN_EPS 1e-5f

// ---------------- scratch ----------------
__device__ float  g_chunk[(size_t)MROWS*CD];          // f32 for LN
__device__ float  g_proj [(size_t)MROWS*CD];          // f32 for LN
__device__ __half g_emb_h  [(size_t)MROWS*CD];
__device__ __half g_chunk_h[(size_t)MROWS*CD];
__device__ __half g_qkv_h  [(size_t)MROWS*3*CD];
__device__ __half g_attn_h [(size_t)MROWS*CD];
__device__ __half g_cw_h[(size_t)CD*2*CD];
__device__ __half g_iw_h[(size_t)3*CD*CD];
__device__ __half g_ow_h[(size_t)CD*CD];

// ---------------- helpers ----------------
__device__ __forceinline__ float ex2f(float x) {
    float y; asm("ex2.approx.f32 %0, %1;" : "=f"(y) : "f"(x)); return y;
}
__device__ __forceinline__ uint32_t pack_f16(float lo, float hi) {
    uint32_t r; asm("cvt.rn.f16x2.f32 %0, %1, %2;" : "=r"(r) : "f"(hi), "f"(lo));
    return r;
}
__device__ __forceinline__ void mma_f16(float c[4], const uint32_t a[4],
                                        const uint32_t b[2]) {
    asm volatile(
        "mma.sync.aligned.m16n8k16.row.col.f32.f16.f16.f32 "
        "{%0,%1,%2,%3}, {%4,%5,%6,%7}, {%8,%9}, {%0,%1,%2,%3};\n"
        : "+f"(c[0]), "+f"(c[1]), "+f"(c[2]), "+f"(c[3])
        : "r"(a[0]), "r"(a[1]), "r"(a[2]), "r"(a[3]), "r"(b[0]), "r"(b[1]));
}
__device__ __forceinline__ void ldsm_x4(uint32_t& r0, uint32_t& r1,
                                        uint32_t& r2, uint32_t& r3,
                                        uint32_t addr) {
    asm volatile("ldmatrix.sync.aligned.m8n8.x4.shared.b16 {%0,%1,%2,%3}, [%4];\n"
                 : "=r"(r0), "=r"(r1), "=r"(r2), "=r"(r3) : "r"(addr));
}
__device__ __forceinline__ void ldsm_x4_t(uint32_t& r0, uint32_t& r1,
                                          uint32_t& r2, uint32_t& r3,
                                          uint32_t addr) {
    asm volatile("ldmatrix.sync.aligned.m8n8.x4.trans.shared.b16 {%0,%1,%2,%3}, [%4];\n"
                 : "=r"(r0), "=r"(r1), "=r"(r2), "=r"(r3) : "r"(addr));
}
__device__ __forceinline__ uint32_t smem_u32(const void* p) {
    return (uint32_t)__cvta_generic_to_shared(p);
}
__device__ __forceinline__ void cp16(uint32_t dst, const void* src) {
    asm volatile("cp.async.cg.shared.global [%0], [%1], 16;\n"
                 :: "r"(dst), "l"(src));
}
__device__ __forceinline__ void cp16z(uint32_t dst, const void* src, int srcsz) {
    asm volatile("cp.async.cg.shared.global [%0], [%1], 16, %2;\n"
                 :: "r"(dst), "l"(src), "r"(srcsz));
}
__device__ __forceinline__ void cp_commit() {
    asm volatile("cp.async.commit_group;\n");
}
template<int N> __device__ __forceinline__ void cp_wait() {
    asm volatile("cp.async.wait_group %0;\n" :: "n"(N));
}

// ---------------------------------------------------------------------------
// f32 -> f16 bulk convert (8 elems/thread)
// ---------------------------------------------------------------------------
__global__ __launch_bounds__(256)
void f2h(const float* __restrict__ in, __half* __restrict__ out, int n8) {
    int i = blockIdx.x * 256 + threadIdx.x;
    if (i < n8) {
        float4 a = ((const float4*)in)[2 * i];
        float4 b = ((const float4*)in)[2 * i + 1];
        uint4 o;
        o.x = pack_f16(a.x, a.y); o.y = pack_f16(a.z, a.w);
        o.z = pack_f16(b.x, b.y); o.w = pack_f16(b.z, b.w);
        ((uint4*)out)[i] = o;
    }
}

// ---------------------------------------------------------------------------
// FP16 NT GEMM: C = A @ B^T + bias  (A,B fp16; accum f32)
// 128x128x32 tile, 256 threads, warp tile 64x32, 3-stage cp.async (R8 ring),
// LDSM fragments, mma.m16n8k16.f16. Optional f32 and/or f16 outputs.
// smem rows padded to 40 halves (80B: conflict-free ldmatrix + aligned cp16).
// ---------------------------------------------------------------------------
#define GSTGH (128 * 40)                 // halves per stage per matrix
#define GH_SMEM (3 * 2 * GSTGH * 2)      // 61440 B

template<bool WINDOW>
__global__ __launch_bounds__(256, 2)
void gemm_f16(const __half* __restrict__ A, const __half* __restrict__ B,
              const float* __restrict__ bias,
              float* __restrict__ Cf, __half* __restrict__ Ch,
              int M, int N, int K) {
    extern __shared__ __half smh[];
    __half* As = smh;                 // [3][128][40]
    __half* Bs = smh + 3 * GSTGH;     // [3][128][40]

    int tid = threadIdx.x;
    int bm = blockIdx.y * 128, bn = blockIdx.x * 128;
    int warp = tid >> 5, lane = tid & 31, gid = lane >> 2, tig = lane & 3;
    int l7 = lane & 7, l3 = lane >> 3;
    int wm = (warp >> 2) * 64, wn = (warp & 3) * 32;

    float acc[4][4][4];
#pragma unroll
    for (int i = 0; i < 4; i++)
#pragma unroll
        for (int j = 0; j < 4; j++)
#pragma unroll
            for (int c = 0; c < 4; c++) acc[i][j][c] = 0.f;

    auto load_stage = [&](int st, int k0) {
#pragma unroll
        for (int p = 0; p < 2; p++) {
            int id  = tid + p * 256;        // 0..511
            int row = id >> 2;              // 0..127
            int kq  = (id & 3) << 3;        // 0,8,16,24 halves
            uint32_t da = smem_u32(&As[st * GSTGH + row * 40 + kq]);
            if (WINDOW) {
                int m = bm + row;
                int bidx = m >> 11, s = m & (CS - 1);
                int f = k0 + kq, kk = f >> 10, j = f & (CD - 1);
                const __half* src = A + (((size_t)bidx * CS + s + kk) << 10) + j;
                cp16z(da, src, (s + kk < CS) ? 16 : 0);
            } else {
                cp16(da, A + (size_t)(bm + row) * K + k0 + kq);
            }
            cp16(smem_u32(&Bs[st * GSTGH + row * 40 + kq]),
                 B + (size_t)(bn + row) * K + k0 + kq);
        }
        cp_commit();
    };

    int nk = K >> 5;
    load_stage(0, 0);
    load_stage(1, 32);

    int st = 0, pfst = 2;
    for (int kc = 0; kc < nk; kc++) {
        cp_wait<1>();
        __syncthreads();

        int pf = kc + 2;
        if (pf < nk) load_stage(pfst, pf << 5);
        else cp_commit();

        uint32_t Abase = smem_u32(As + st * GSTGH);
        uint32_t Bbase = smem_u32(Bs + st * GSTGH);
#pragma unroll
        for (int g = 0; g < 32; g += 16) {
            uint32_t a[4][4], bf[4][2];
#pragma unroll
            for (int ti = 0; ti < 4; ti++) {
                uint32_t adr = Abase +
                    ((wm + ti * 16 + (l3 & 1) * 8 + l7) * 40 +
                     g + (l3 >> 1) * 8) * 2;
                ldsm_x4(a[ti][0], a[ti][1], a[ti][2], a[ti][3], adr);
            }
#pragma unroll
            for (int tp = 0; tp < 2; tp++) {
                uint32_t adr = Bbase +
                    ((wn + tp * 16 + (l3 & 1) * 8 + l7) * 40 +
                     g + (l3 >> 1) * 8) * 2;
                uint32_t r0, r1, r2, r3;
                ldsm_x4(r0, r1, r2, r3, adr);
                bf[2 * tp][0] = r0; bf[2 * tp][1] = r2;       // n-lo tile
                bf[2 * tp + 1][0] = r1; bf[2 * tp + 1][1] = r3; // n-hi tile
            }
#pragma unroll
            for (int ti = 0; ti < 4; ti++)
#pragma unroll
                for (int tj = 0; tj < 4; tj++)
                    mma_f16(acc[ti][tj], a[ti], bf[tj]);
        }

        st   = (st   == 2) ? 0 : st + 1;
        pfst = (pfst == 2) ? 0 : pfst + 1;
    }

#pragma unroll
    for (int ti = 0; ti < 4; ti++) {
#pragma unroll
        for (int hh = 0; hh < 2; hh++) {
            int row = bm + wm + ti * 16 + gid + 8 * hh;
#pragma unroll
            for (int tj = 0; tj < 4; tj++) {
                int col = bn + wn + tj * 8 + 2 * tig;
                float ox = acc[ti][tj][2 * hh + 0] + bias[col + 0];
                float oy = acc[ti][tj][2 * hh + 1] + bias[col + 1];
                if (Cf) *(float2*)&Cf[(size_t)row * N + col] = make_float2(ox, oy);
                if (Ch) *(uint32_t*)&Ch[(size_t)row * N + col] = pack_f16(ox, oy);
            }
        }
    }
}

// ---------------------------------------------------------------------------
// FP16 flash attention. 8 warps x 16 q-rows (R8 shape), 2 CTAs/SM.
// qkv fp16 in gmem -> cp.async straight to smem, no conversion passes.
// kv tiles of 64, 3-stage ring. S & PV both mma.f16; qscale folded pre-exp.
// Row-sums via ones-column. Output attn fp16.
// ---------------------------------------------------------------------------
#define FKV (64 * 72)                       // halves per stage per matrix
#define FA_SMEM (3 * 2 * FKV * 2)           // 55296 B

__global__ __launch_bounds__(256, 2)
void flash_f16(const __half* __restrict__ qkv, __half* __restrict__ out) {
    extern __shared__ __half smh[];
    __half* Ks = smh;                 // [3][64][72]
    __half* Vs = smh + 3 * FKV;       // [3][64][72]

    int b = blockIdx.y >> 4, h = blockIdx.y & 15;
    int q0 = blockIdx.x << 7;
    int tid = threadIdx.x, warp = tid >> 5, lane = tid & 31;
    int gid = lane >> 2, tig = lane & 3;
    int wq = warp * 16;
    int l7 = lane & 7, l3 = lane >> 3;

    const size_t rstr = 3 * CD;
    const __half* qb = qkv + (size_t)b * CS * rstr + h * CDH;
    const __half* kb = qb + CD;
    const __half* vb = qb + 2 * CD;
    const float qscale = 1.4426950408889634f * 0.125f;   // log2e / sqrt(dh)

    // ---- stage Q through the first two K stages (128*72 == 2*FKV)
#pragma unroll
    for (int p = 0; p < 4; p++) {
        int id  = tid + p * 256;        // 0..1023
        int row = id >> 3;              // 0..127
        int c8  = (id & 7) << 3;        // 0..56
        cp16(smem_u32(&Ks[row * 72 + c8]),
             qb + (size_t)(q0 + row) * rstr + c8);
    }
    cp_commit();
    cp_wait<0>();
    __syncthreads();

    uint32_t Qbase = smem_u32(Ks);
    uint32_t qf[4][4];
#pragma unroll
    for (int g4 = 0; g4 < 4; g4++) {
        uint32_t adr = Qbase +
            ((wq + (l3 & 1) * 8 + l7) * 72 + g4 * 16 + (l3 >> 1) * 8) * 2;
        ldsm_x4(qf[g4][0], qf[g4][1], qf[g4][2], qf[g4][3], adr);
    }
    __syncthreads();

    auto load_kv = [&](int st, int kt) {
#pragma unroll
        for (int p = 0; p < 2; p++) {
            int id  = tid + p * 256;    // 0..511
            int row = id >> 3;          // 0..63
            int c8  = (id & 7) << 3;
            cp16(smem_u32(&Ks[st * FKV + row * 72 + c8]),
                 kb + (size_t)(kt + row) * rstr + c8);
            cp16(smem_u32(&Vs[st * FKV + row * 72 + c8]),
                 vb + (size_t)(kt + row) * rstr + c8);
        }
        cp_commit();
    };

    load_kv(0, 0);
    load_kv(1, 64);

    float o[9][4];
#pragma unroll
    for (int n = 0; n < 9; n++)
#pragma unroll
        for (int c = 0; c < 4; c++) o[n][c] = 0.f;

    const uint32_t bones = (gid == 0) ? 0x3C003C00u : 0u;   // fp16 {1,1}
    const int nkt = CS / 64;   // 32

    for (int it = 0; it < nkt; it++) {
        __syncthreads();    // all warps done reading slot (it-1)%3
        if (it + 2 < nkt) load_kv((it + 2) % 3, (it + 2) * 64);
        else cp_commit();
        cp_wait<2>();       // stage it resident
        __syncthreads();

        int slot = it % 3;
        uint32_t Kbase = smem_u32(Ks + slot * FKV);
        uint32_t Vbase = smem_u32(Vs + slot * FKV);

        // S = Q @ K^T : 8 independent chains of depth 4
        float sc[8][4];
#pragma unroll
        for (int n = 0; n < 8; n++)
#pragma unroll
            for (int c = 0; c < 4; c++) sc[n][c] = 0.f;
#pragma unroll
        for (int g4 = 0; g4 < 4; g4++) {
#pragma unroll
            for (int np = 0; np < 4; np++) {
                uint32_t adr = Kbase +
                    ((np * 16 + (l3 & 1) * 8 + l7) * 72 +
                     g4 * 16 + (l3 >> 1) * 8) * 2;
                uint32_t r0, r1, r2, r3;
                ldsm_x4(r0, r1, r2, r3, adr);
                uint32_t b0[2] = {r0, r2};
                uint32_t b1[2] = {r1, r3};
                mma_f16(sc[2 * np],     qf[g4], b0);
                mma_f16(sc[2 * np + 1], qf[g4], b1);
            }
        }

        // P = exp2(S * qscale) packed into fp16 A-fragments
        uint32_t pf[4][4];
#pragma unroll
        for (int n = 0; n < 8; n++) {
            int t = n >> 1, hi = (n & 1) << 1;
            pf[t][hi + 0] = pack_f16(ex2f(sc[n][0] * qscale),
                                     ex2f(sc[n][1] * qscale));
            pf[t][hi + 1] = pack_f16(ex2f(sc[n][2] * qscale),
                                     ex2f(sc[n][3] * qscale));
        }

        // O += P @ V  (V via ldmatrix.trans, fp16)
#pragma unroll
        for (int t = 0; t < 4; t++) {
#pragma unroll
            for (int a = 0; a < 4; a++) {
                uint32_t adr = Vbase +
                    (16 * t + (l3 & 1) * 8 + l7) * 144 +
                    (2 * a + (l3 >> 1)) * 16;
                uint32_t v0, v1, v2, v3;
                ldsm_x4_t(v0, v1, v2, v3, adr);
                uint32_t bv0[2] = {v0, v1};
                uint32_t bv1[2] = {v2, v3};
                mma_f16(o[2 * a],     pf[t], bv0);
                mma_f16(o[2 * a + 1], pf[t], bv1);
            }
            {
                uint32_t bv[2] = {bones, bones};
                mma_f16(o[8], pf[t], bv);
            }
        }
    }

    // normalize + write fp16 (row sums in tig==0 lanes of o[8])
    int base = lane & 28;
#pragma unroll
    for (int hh = 0; hh < 2; hh++) {
        float lsv = __shfl_sync(0xffffffffu, o[8][hh ? 2 : 0], base);
        float inv = 1.f / lsv;
        int row = q0 + wq + gid + 8 * hh;
#pragma unroll
        for (int n = 0; n < 8; n++) {
            int col = h * CDH + n * 8 + 2 * tig;
            *(uint32_t*)&out[((size_t)b * CS + row) * CD + col] =
                pack_f16(o[n][2 * hh] * inv, o[n][2 * hh + 1] * inv);
        }
    }
}

// ---------------------------------------------------------------------------
// Fused residual add + LayerNorm
// ---------------------------------------------------------------------------
__global__ __launch_bounds__(256)
void add_ln(const float* __restrict__ chunk, const float* __restrict__ proj,
            const float* __restrict__ g, const float* __restrict__ beta,
            float* __restrict__ out) {
    int row = blockIdx.x;
    int tid = threadIdx.x;
    size_t base = (size_t)row * CD + tid * 4;

    float4 c = *(const float4*)&chunk[base];
    float4 p = *(const float4*)&proj[base];
    float4 x = make_float4(c.x + p.x, c.y + p.y, c.z + p.z, c.w + p.w);

    float s  = x.x + x.y + x.z + x.w;
    float s2 = x.x * x.x + x.y * x.y + x.z * x.z + x.w * x.w;
#pragma unroll
    for (int off = 16; off; off >>= 1) {
        s  += __shfl_xor_sync(0xffffffffu, s,  off);
        s2 += __shfl_xor_sync(0xffffffffu, s2, off);
    }
    __shared__ float rs[8], rs2[8];
    __shared__ float s_mu, s_rstd;
    int lane = tid & 31, warp = tid >> 5;
    if (lane == 0) { rs[warp] = s; rs2[warp] = s2; }
    __syncthreads();
    if (tid == 0) {
        float a = 0.f, b2 = 0.f;
#pragma unroll
        for (int w = 0; w < 8; w++) { a += rs[w]; b2 += rs2[w]; }
        float mean = a * (1.f / CD);
        float var  = b2 * (1.f / CD) - mean * mean;
        s_mu = mean;
        s_rstd = rsqrtf(var + LN_EPS);
    }
    __syncthreads();
    float mu = s_mu, rstd = s_rstd;

    float4 gv = *(const float4*)&g[tid * 4];
    float4 bv = *(const float4*)&beta[tid * 4];
    float4 y;
    y.x = (x.x - mu) * rstd * gv.x + bv.x;
    y.y = (x.y - mu) * rstd * gv.y + bv.y;
    y.z = (x.z - mu) * rstd * gv.z + bv.z;
    y.w = (x.w - mu) * rstd * gv.w + bv.w;
    *(float4*)&out[base] = y;
}

// ---------------------------------------------------------------------------
extern "C" void kernel_launch(void* const* d_in, const int* in_sizes, int n_in,
                              void* d_out, int out_size) {
    const float* emb     = (const float*)d_in[0];
    const float* chunk_w = (const float*)d_in[1];
    const float* chunk_b = (const float*)d_in[2];
    const float* in_w    = (const float*)d_in[3];
    const float* in_b    = (const float*)d_in[4];
    const float* out_w   = (const float*)d_in[5];
    const float* out_b   = (const float*)d_in[6];
    const float* ln_g    = (const float*)d_in[7];
    const float* ln_b    = (const float*)d_in[8];
    float* out = (float*)d_out;

    float *chunk, *proj;
    __half *emb_h, *chunk_h, *qkv_h, *attn_h, *cw_h, *iw_h, *ow_h;
    cudaGetSymbolAddress((void**)&chunk,   g_chunk);
    cudaGetSymbolAddress((void**)&proj,    g_proj);
    cudaGetSymbolAddress((void**)&emb_h,   g_emb_h);
    cudaGetSymbolAddress((void**)&chunk_h, g_chunk_h);
    cudaGetSymbolAddress((void**)&qkv_h,   g_qkv_h);
    cudaGetSymbolAddress((void**)&attn_h,  g_attn_h);
    cudaGetSymbolAddress((void**)&cw_h,    g_cw_h);
    cudaGetSymbolAddress((void**)&iw_h,    g_iw_h);
    cudaGetSymbolAddress((void**)&ow_h,    g_ow_h);

    cudaFuncSetAttribute(gemm_f16<true>,
                         cudaFuncAttributeMaxDynamicSharedMemorySize, GH_SMEM);
    cudaFuncSetAttribute(gemm_f16<false>,
                         cudaFuncAttributeMaxDynamicSharedMemorySize, GH_SMEM);
    cudaFuncSetAttribute(flash_f16,
                         cudaFuncAttributeMaxDynamicSharedMemorySize, FA_SMEM);

    // 0) f32 -> f16 conversions
    {
        int n;
        n = MROWS * CD / 8;      f2h<<<(n + 255) / 256, 256>>>(emb, emb_h, n);
        n = CD * 2 * CD / 8;     f2h<<<(n + 255) / 256, 256>>>(chunk_w, cw_h, n);
        n = 3 * CD * CD / 8;     f2h<<<(n + 255) / 256, 256>>>(in_w, iw_h, n);
        n = CD * CD / 8;         f2h<<<(n + 255) / 256, 256>>>(out_w, ow_h, n);
    }
    // 1) chunk = windows @ chunk_w^T + chunk_b  (f32 + f16 outputs)
    {
        dim3 grid(CD / 128, MROWS / 128);
        gemm_f16<true><<<grid, 256, GH_SMEM>>>(emb_h, cw_h, chunk_b,
                                               chunk, chunk_h,
                                               MROWS, CD, 2 * CD);
    }
    // 2) qkv = chunk @ in_proj_w^T + in_proj_b  (f16 output only)
    {
        dim3 grid(3 * CD / 128, MROWS / 128);
        gemm_f16<false><<<grid, 256, GH_SMEM>>>(chunk_h, iw_h, in_b,
                                                nullptr, qkv_h,
                                                MROWS, 3 * CD, CD);
    }
    // 3) flash attention (fp16 in/out)
    {
        dim3 grid(CS / 128, CB * CH);
        flash_f16<<<grid, 256, FA_SMEM>>>(qkv_h, attn_h);
    }
    // 4) proj = attn @ out_proj_w^T + out_proj_b  (f32 output only)
    {
        dim3 grid(CD / 128, MROWS / 128);
        gemm_f16<false><<<grid, 256, GH_SMEM>>>(attn_h, ow_h, out_b,
                                                proj, nullptr,
                                                MROWS, CD, CD);
    }
    // 5) out = LayerNorm(chunk + proj)
    add_ln<<<MROWS, 256>>>(chunk, proj, ln_g, ln_b, out);
}

// round 12
// speedup vs baseline: 1.5726x; 1.0694x over previous
#include <cuda_runtime.h>
#include <cuda_fp16.h>
#include <math.h>
#include <stdint.h>

#define CB   4
#define CS   2048
#define CD   1024
#define CH   16
#define CDH  64
#define MROWS (CB*CS)
#define LN_EPS 1e-5f

// ---------------- scratch ----------------
__device__ float  g_chunk[(size_t)MROWS*CD];          // f32 for LN
__device__ float  g_proj [(size_t)MROWS*CD];          // f32 for LN
__device__ __half g_emb_h  [(size_t)MROWS*CD];
__device__ __half g_chunk_h[(size_t)MROWS*CD];
__device__ __half g_qkv_h  [(size_t)MROWS*3*CD];
__device__ __half g_attn_h [(size_t)MROWS*CD];
__device__ __half g_cw_h[(size_t)CD*2*CD];
__device__ __half g_iw_h[(size_t)3*CD*CD];
__device__ __half g_ow_h[(size_t)CD*CD];

// ---------------- helpers ----------------
__device__ __forceinline__ float ex2f(float x) {
    float y; asm("ex2.approx.f32 %0, %1;" : "=f"(y) : "f"(x)); return y;
}
__device__ __forceinline__ uint32_t pack_f16(float lo, float hi) {
    uint32_t r; asm("cvt.rn.f16x2.f32 %0, %1, %2;" : "=r"(r) : "f"(hi), "f"(lo));
    return r;
}
__device__ __forceinline__ void mma_f16(float c[4], const uint32_t a[4],
                                        const uint32_t b[2]) {
    asm volatile(
        "mma.sync.aligned.m16n8k16.row.col.f32.f16.f16.f32 "
        "{%0,%1,%2,%3}, {%4,%5,%6,%7}, {%8,%9}, {%0,%1,%2,%3};\n"
        : "+f"(c[0]), "+f"(c[1]), "+f"(c[2]), "+f"(c[3])
        : "r"(a[0]), "r"(a[1]), "r"(a[2]), "r"(a[3]), "r"(b[0]), "r"(b[1]));
}
__device__ __forceinline__ void ldsm_x4(uint32_t& r0, uint32_t& r1,
                                        uint32_t& r2, uint32_t& r3,
                                        uint32_t addr) {
    asm volatile("ldmatrix.sync.aligned.m8n8.x4.shared.b16 {%0,%1,%2,%3}, [%4];\n"
                 : "=r"(r0), "=r"(r1), "=r"(r2), "=r"(r3) : "r"(addr));
}
__device__ __forceinline__ void ldsm_x4_t(uint32_t& r0, uint32_t& r1,
                                          uint32_t& r2, uint32_t& r3,
                                          uint32_t addr) {
    asm volatile("ldmatrix.sync.aligned.m8n8.x4.trans.shared.b16 {%0,%1,%2,%3}, [%4];\n"
                 : "=r"(r0), "=r"(r1), "=r"(r2), "=r"(r3) : "r"(addr));
}
__device__ __forceinline__ uint32_t smem_u32(const void* p) {
    return (uint32_t)__cvta_generic_to_shared(p);
}
__device__ __forceinline__ void cp16(uint32_t dst, const void* src) {
    asm volatile("cp.async.cg.shared.global [%0], [%1], 16;\n"
                 :: "r"(dst), "l"(src));
}
__device__ __forceinline__ void cp16z(uint32_t dst, const void* src, int srcsz) {
    asm volatile("cp.async.cg.shared.global [%0], [%1], 16, %2;\n"
                 :: "r"(dst), "l"(src), "r"(srcsz));
}
__device__ __forceinline__ void cp_commit() {
    asm volatile("cp.async.commit_group;\n");
}
template<int N> __device__ __forceinline__ void cp_wait() {
    asm volatile("cp.async.wait_group %0;\n" :: "n"(N));
}

// ---------------------------------------------------------------------------
// f32 -> f16 bulk convert (8 elems/thread)
// ---------------------------------------------------------------------------
__global__ __launch_bounds__(256)
void f2h(const float* __restrict__ in, __half* __restrict__ out, int n8) {
    int i = blockIdx.x * 256 + threadIdx.x;
    if (i < n8) {
        float4 a = ((const float4*)in)[2 * i];
        float4 b = ((const float4*)in)[2 * i + 1];
        uint4 o;
        o.x = pack_f16(a.x, a.y); o.y = pack_f16(a.z, a.w);
        o.z = pack_f16(b.x, b.y); o.w = pack_f16(b.z, b.w);
        ((uint4*)out)[i] = o;
    }
}

// ---------------------------------------------------------------------------
// FP16 NT GEMM: C = A @ B^T + bias  (A,B fp16; accum f32)
// 128x128x64 tile, 256 threads, warp tile 64x32, 3-stage cp.async ring,
// LDSM fragments, mma.m16n8k16.f16. Rows padded to 72 halves.
// ---------------------------------------------------------------------------
#define GSTGH (128 * 72)                 // halves per stage per matrix
#define GH_SMEM (3 * 2 * GSTGH * 2)      // 110592 B

template<bool WINDOW>
__global__ __launch_bounds__(256, 2)
void gemm_f16(const __half* __restrict__ A, const __half* __restrict__ B,
              const float* __restrict__ bias,
              float* __restrict__ Cf, __half* __restrict__ Ch,
              int M, int N, int K) {
    extern __shared__ __half smh[];
    __half* As = smh;                 // [3][128][72]
    __half* Bs = smh + 3 * GSTGH;     // [3][128][72]

    int tid = threadIdx.x;
    int bm = blockIdx.y * 128, bn = blockIdx.x * 128;
    int warp = tid >> 5, lane = tid & 31, gid = lane >> 2, tig = lane & 3;
    int l7 = lane & 7, l3 = lane >> 3;
    int wm = (warp >> 2) * 64, wn = (warp & 3) * 32;

    float acc[4][4][4];
#pragma unroll
    for (int i = 0; i < 4; i++)
#pragma unroll
        for (int j = 0; j < 4; j++)
#pragma unroll
            for (int c = 0; c < 4; c++) acc[i][j][c] = 0.f;

    auto load_stage = [&](int st, int k0) {
#pragma unroll
        for (int p = 0; p < 4; p++) {
            int id  = tid + p * 256;        // 0..1023
            int row = id >> 3;              // 0..127
            int kq  = (id & 7) << 3;        // 0..56 halves
            uint32_t da = smem_u32(&As[st * GSTGH + row * 72 + kq]);
            if (WINDOW) {
                int m = bm + row;
                int bidx = m >> 11, s = m & (CS - 1);
                int f = k0 + kq, kk = f >> 10, j = f & (CD - 1);
                const __half* src = A + (((size_t)bidx * CS + s + kk) << 10) + j;
                cp16z(da, src, (s + kk < CS) ? 16 : 0);
            } else {
                cp16(da, A + (size_t)(bm + row) * K + k0 + kq);
            }
            cp16(smem_u32(&Bs[st * GSTGH + row * 72 + kq]),
                 B + (size_t)(bn + row) * K + k0 + kq);
        }
        cp_commit();
    };

    int nk = K >> 6;   // BK=64; >= 3 for all our shapes
    load_stage(0, 0);
    load_stage(1, 64);

    int st = 0, pfst = 2;
    for (int kc = 0; kc < nk; kc++) {
        cp_wait<1>();
        __syncthreads();

        int pf = kc + 2;
        if (pf < nk) load_stage(pfst, pf << 6);
        else cp_commit();

        uint32_t Abase = smem_u32(As + st * GSTGH);
        uint32_t Bbase = smem_u32(Bs + st * GSTGH);
#pragma unroll
        for (int g = 0; g < 64; g += 16) {
            uint32_t a[4][4], bf[4][2];
#pragma unroll
            for (int ti = 0; ti < 4; ti++) {
                uint32_t adr = Abase +
                    ((wm + ti * 16 + (l3 & 1) * 8 + l7) * 72 +
                     g + (l3 >> 1) * 8) * 2;
                ldsm_x4(a[ti][0], a[ti][1], a[ti][2], a[ti][3], adr);
            }
#pragma unroll
            for (int tp = 0; tp < 2; tp++) {
                uint32_t adr = Bbase +
                    ((wn + tp * 16 + (l3 & 1) * 8 + l7) * 72 +
                     g + (l3 >> 1) * 8) * 2;
                uint32_t r0, r1, r2, r3;
                ldsm_x4(r0, r1, r2, r3, adr);
                bf[2 * tp][0] = r0; bf[2 * tp][1] = r2;
                bf[2 * tp + 1][0] = r1; bf[2 * tp + 1][1] = r3;
            }
#pragma unroll
            for (int ti = 0; ti < 4; ti++)
#pragma unroll
                for (int tj = 0; tj < 4; tj++)
                    mma_f16(acc[ti][tj], a[ti], bf[tj]);
        }

        st   = (st   == 2) ? 0 : st + 1;
        pfst = (pfst == 2) ? 0 : pfst + 1;
    }

#pragma unroll
    for (int ti = 0; ti < 4; ti++) {
#pragma unroll
        for (int hh = 0; hh < 2; hh++) {
            int row = bm + wm + ti * 16 + gid + 8 * hh;
#pragma unroll
            for (int tj = 0; tj < 4; tj++) {
                int col = bn + wn + tj * 8 + 2 * tig;
                float ox = acc[ti][tj][2 * hh + 0] + bias[col + 0];
                float oy = acc[ti][tj][2 * hh + 1] + bias[col + 1];
                if (Cf) *(float2*)&Cf[(size_t)row * N + col] = make_float2(ox, oy);
                if (Ch) *(uint32_t*)&Ch[(size_t)row * N + col] = pack_f16(ox, oy);
            }
        }
    }
}

// ---------------------------------------------------------------------------
// FP16 flash attention. 8 warps x 16 q-rows, 2 CTAs/SM.
// kv tiles of 128 (two 64-row halves with the proven R11 inner code),
// 2-stage ring -> one cp_wait + 2 barriers per 128 kv rows.
// ---------------------------------------------------------------------------
#define FKV (128 * 72)                      // halves per stage per matrix
#define FA_SMEM (2 * 2 * FKV * 2)           // 73728 B

__global__ __launch_bounds__(256, 2)
void flash_f16(const __half* __restrict__ qkv, __half* __restrict__ out) {
    extern __shared__ __half smh[];
    __half* Ks = smh;                 // [2][128][72]
    __half* Vs = smh + 2 * FKV;       // [2][128][72]

    int b = blockIdx.y >> 4, h = blockIdx.y & 15;
    int q0 = blockIdx.x << 7;
    int tid = threadIdx.x, warp = tid >> 5, lane = tid & 31;
    int gid = lane >> 2, tig = lane & 3;
    int wq = warp * 16;
    int l7 = lane & 7, l3 = lane >> 3;

    const size_t rstr = 3 * CD;
    const __half* qb = qkv + (size_t)b * CS * rstr + h * CDH;
    const __half* kb = qb + CD;
    const __half* vb = qb + 2 * CD;
    const float qscale = 1.4426950408889634f * 0.125f;   // log2e / sqrt(dh)

    // ---- stage Q through kv-stage 0 (128*72 fits exactly)
#pragma unroll
    for (int p = 0; p < 4; p++) {
        int id  = tid + p * 256;        // 0..1023
        int row = id >> 3;              // 0..127
        int c8  = (id & 7) << 3;        // 0..56
        cp16(smem_u32(&Ks[row * 72 + c8]),
             qb + (size_t)(q0 + row) * rstr + c8);
    }
    cp_commit();
    cp_wait<0>();
    __syncthreads();

    uint32_t Qbase = smem_u32(Ks);
    uint32_t qf[4][4];
#pragma unroll
    for (int g4 = 0; g4 < 4; g4++) {
        uint32_t adr = Qbase +
            ((wq + (l3 & 1) * 8 + l7) * 72 + g4 * 16 + (l3 >> 1) * 8) * 2;
        ldsm_x4(qf[g4][0], qf[g4][1], qf[g4][2], qf[g4][3], adr);
    }
    __syncthreads();

    auto load_kv = [&](int st, int kt) {
#pragma unroll
        for (int p = 0; p < 4; p++) {
            int id  = tid + p * 256;    // 0..1023
            int row = id >> 3;          // 0..127
            int c8  = (id & 7) << 3;
            cp16(smem_u32(&Ks[st * FKV + row * 72 + c8]),
                 kb + (size_t)(kt + row) * rstr + c8);
            cp16(smem_u32(&Vs[st * FKV + row * 72 + c8]),
                 vb + (size_t)(kt + row) * rstr + c8);
        }
        cp_commit();
    };

    load_kv(0, 0);
    load_kv(1, 128);

    float o[9][4];
#pragma unroll
    for (int n = 0; n < 9; n++)
#pragma unroll
        for (int c = 0; c < 4; c++) o[n][c] = 0.f;

    const uint32_t bones = (gid == 0) ? 0x3C003C00u : 0u;   // fp16 {1,1}
    const int nkt = CS / 128;   // 16

    for (int it = 0; it < nkt; it++) {
        int st = it & 1;
        cp_wait<1>();
        __syncthreads();

#pragma unroll
        for (int half = 0; half < 2; half++) {
            uint32_t Kbase = smem_u32(Ks + st * FKV + half * 64 * 72);
            uint32_t Vbase = smem_u32(Vs + st * FKV + half * 64 * 72);

            // S = Q @ K^T : 8 independent chains of depth 4
            float sc[8][4];
#pragma unroll
            for (int n = 0; n < 8; n++)
#pragma unroll
                for (int c = 0; c < 4; c++) sc[n][c] = 0.f;
#pragma unroll
            for (int g4 = 0; g4 < 4; g4++) {
#pragma unroll
                for (int np = 0; np < 4; np++) {
                    uint32_t adr = Kbase +
                        ((np * 16 + (l3 & 1) * 8 + l7) * 72 +
                         g4 * 16 + (l3 >> 1) * 8) * 2;
                    uint32_t r0, r1, r2, r3;
                    ldsm_x4(r0, r1, r2, r3, adr);
                    uint32_t b0[2] = {r0, r2};
                    uint32_t b1[2] = {r1, r3};
                    mma_f16(sc[2 * np],     qf[g4], b0);
                    mma_f16(sc[2 * np + 1], qf[g4], b1);
                }
            }

            // P = exp2(S * qscale) packed into fp16 A-fragments
            uint32_t pf[4][4];
#pragma unroll
            for (int n = 0; n < 8; n++) {
                int t = n >> 1, hi = (n & 1) << 1;
                pf[t][hi + 0] = pack_f16(ex2f(sc[n][0] * qscale),
                                         ex2f(sc[n][1] * qscale));
                pf[t][hi + 1] = pack_f16(ex2f(sc[n][2] * qscale),
                                         ex2f(sc[n][3] * qscale));
            }

            // O += P @ V  (V via ldmatrix.trans)
#pragma unroll
            for (int t = 0; t < 4; t++) {
#pragma unroll
                for (int a = 0; a < 4; a++) {
                    uint32_t adr = Vbase +
                        (16 * t + (l3 & 1) * 8 + l7) * 144 +
                        (2 * a + (l3 >> 1)) * 16;
                    uint32_t v0, v1, v2, v3;
                    ldsm_x4_t(v0, v1, v2, v3, adr);
                    uint32_t bv0[2] = {v0, v1};
                    uint32_t bv1[2] = {v2, v3};
                    mma_f16(o[2 * a],     pf[t], bv0);
                    mma_f16(o[2 * a + 1], pf[t], bv1);
                }
                {
                    uint32_t bv[2] = {bones, bones};
                    mma_f16(o[8], pf[t], bv);
                }
            }
        }

        __syncthreads();
        if (it + 2 < nkt) load_kv(st, (it + 2) * 128);
        else cp_commit();
    }

    // normalize + write fp16 (row sums in tig==0 lanes of o[8])
    int base = lane & 28;
#pragma unroll
    for (int hh = 0; hh < 2; hh++) {
        float lsv = __shfl_sync(0xffffffffu, o[8][hh ? 2 : 0], base);
        float inv = 1.f / lsv;
        int row = q0 + wq + gid + 8 * hh;
#pragma unroll
        for (int n = 0; n < 8; n++) {
            int col = h * CDH + n * 8 + 2 * tig;
            *(uint32_t*)&out[((size_t)b * CS + row) * CD + col] =
                pack_f16(o[n][2 * hh] * inv, o[n][2 * hh + 1] * inv);
        }
    }
}

// ---------------------------------------------------------------------------
// Fused residual add + LayerNorm
// ---------------------------------------------------------------------------
__global__ __launch_bounds__(256)
void add_ln(const float* __restrict__ chunk, const float* __restrict__ proj,
            const float* __restrict__ g, const float* __restrict__ beta,
            float* __restrict__ out) {
    int row = blockIdx.x;
    int tid = threadIdx.x;
    size_t base = (size_t)row * CD + tid * 4;

    float4 c = *(const float4*)&chunk[base];
    float4 p = *(const float4*)&proj[base];
    float4 x = make_float4(c.x + p.x, c.y + p.y, c.z + p.z, c.w + p.w);

    float s  = x.x + x.y + x.z + x.w;
    float s2 = x.x * x.x + x.y * x.y + x.z * x.z + x.w * x.w;
#pragma unroll
    for (int off = 16; off; off >>= 1) {
        s  += __shfl_xor_sync(0xffffffffu, s,  off);
        s2 += __shfl_xor_sync(0xffffffffu, s2, off);
    }
    __shared__ float rs[8], rs2[8];
    __shared__ float s_mu, s_rstd;
    int lane = tid & 31, warp = tid >> 5;
    if (lane == 0) { rs[warp] = s; rs2[warp] = s2; }
    __syncthreads();
    if (tid == 0) {
        float a = 0.f, b2 = 0.f;
#pragma unroll
        for (int w = 0; w < 8; w++) { a += rs[w]; b2 += rs2[w]; }
        float mean = a * (1.f / CD);
        float var  = b2 * (1.f / CD) - mean * mean;
        s_mu = mean;
        s_rstd = rsqrtf(var + LN_EPS);
    }
    __syncthreads();
    float mu = s_mu, rstd = s_rstd;

    float4 gv = *(const float4*)&g[tid * 4];
    float4 bv = *(const float4*)&beta[tid * 4];
    float4 y;
    y.x = (x.x - mu) * rstd * gv.x + bv.x;
    y.y = (x.y - mu) * rstd * gv.y + bv.y;
    y.z = (x.z - mu) * rstd * gv.z + bv.z;
    y.w = (x.w - mu) * rstd * gv.w + bv.w;
    *(float4*)&out[base] = y;
}

// ---------------------------------------------------------------------------
extern "C" void kernel_launch(void* const* d_in, const int* in_sizes, int n_in,
                              void* d_out, int out_size) {
    const float* emb     = (const float*)d_in[0];
    const float* chunk_w = (const float*)d_in[1];
    const float* chunk_b = (const float*)d_in[2];
    const float* in_w    = (const float*)d_in[3];
    const float* in_b    = (const float*)d_in[4];
    const float* out_w   = (const float*)d_in[5];
    const float* out_b   = (const float*)d_in[6];
    const float* ln_g    = (const float*)d_in[7];
    const float* ln_b    = (const float*)d_in[8];
    float* out = (float*)d_out;

    float *chunk, *proj;
    __half *emb_h, *chunk_h, *qkv_h, *attn_h, *cw_h, *iw_h, *ow_h;
    cudaGetSymbolAddress((void**)&chunk,   g_chunk);
    cudaGetSymbolAddress((void**)&proj,    g_proj);
    cudaGetSymbolAddress((void**)&emb_h,   g_emb_h);
    cudaGetSymbolAddress((void**)&chunk_h, g_chunk_h);
    cudaGetSymbolAddress((void**)&qkv_h,   g_qkv_h);
    cudaGetSymbolAddress((void**)&attn_h,  g_attn_h);
    cudaGetSymbolAddress((void**)&cw_h,    g_cw_h);
    cudaGetSymbolAddress((void**)&iw_h,    g_iw_h);
    cudaGetSymbolAddress((void**)&ow_h,    g_ow_h);

    cudaFuncSetAttribute(gemm_f16<true>,
                         cudaFuncAttributeMaxDynamicSharedMemorySize, GH_SMEM);
    cudaFuncSetAttribute(gemm_f16<false>,
                         cudaFuncAttributeMaxDynamicSharedMemorySize, GH_SMEM);
    cudaFuncSetAttribute(flash_f16,
                         cudaFuncAttributeMaxDynamicSharedMemorySize, FA_SMEM);

    // 0) f32 -> f16 conversions
    {
        int n;
        n = MROWS * CD / 8;      f2h<<<(n + 255) / 256, 256>>>(emb, emb_h, n);
        n = CD * 2 * CD / 8;     f2h<<<(n + 255) / 256, 256>>>(chunk_w, cw_h, n);
        n = 3 * CD * CD / 8;     f2h<<<(n + 255) / 256, 256>>>(in_w, iw_h, n);
        n = CD * CD / 8;         f2h<<<(n + 255) / 256, 256>>>(out_w, ow_h, n);
    }
    // 1) chunk = windows @ chunk_w^T + chunk_b  (f32 + f16 outputs)
    {
        dim3 grid(CD / 128, MROWS / 128);
        gemm_f16<true><<<grid, 256, GH_SMEM>>>(emb_h, cw_h, chunk_b,
                                               chunk, chunk_h,
                                               MROWS, CD, 2 * CD);
    }
    // 2) qkv = chunk @ in_proj_w^T + in_proj_b  (f16 output only)
    {
        dim3 grid(3 * CD / 128, MROWS / 128);
        gemm_f16<false><<<grid, 256, GH_SMEM>>>(chunk_h, iw_h, in_b,
                                                nullptr, qkv_h,
                                                MROWS, 3 * CD, CD);
    }
    // 3) flash attention (fp16 in/out)
    {
        dim3 grid(CS / 128, CB * CH);
        flash_f16<<<grid, 256, FA_SMEM>>>(qkv_h, attn_h);
    }
    // 4) proj = attn @ out_proj_w^T + out_proj_b  (f32 output only)
    {
        dim3 grid(CD / 128, MROWS / 128);
        gemm_f16<false><<<grid, 256, GH_SMEM>>>(attn_h, ow_h, out_b,
                                                proj, nullptr,
                                                MROWS, CD, CD);
    }
    // 5) out = LayerNorm(chunk + proj)
    add_ln<<<MROWS, 256>>>(chunk, proj, ln_g, ln_b, out);
}

// round 13
// speedup vs baseline: 1.5893x; 1.0106x over previous
#include <cuda_runtime.h>
#include <cuda_fp16.h>
#include <math.h>
#include <stdint.h>

#define CB   4
#define CS   2048
#define CD   1024
#define CH   16
#define CDH  64
#define MROWS (CB*CS)
#define LN_EPS 1e-5f

// ---------------- scratch ----------------
__device__ float  g_chunk[(size_t)MROWS*CD];          // f32 for LN
__device__ float  g_proj [(size_t)MROWS*CD];          // f32 for LN
__device__ __half g_emb_h  [(size_t)MROWS*CD];
__device__ __half g_chunk_h[(size_t)MROWS*CD];
__device__ __half g_qkv_h  [(size_t)MROWS*3*CD];
__device__ __half g_attn_h [(size_t)MROWS*CD];
__device__ __half g_cw_h[(size_t)CD*2*CD];
__device__ __half g_iw_h[(size_t)3*CD*CD];
__device__ __half g_ow_h[(size_t)CD*CD];

// ---------------- helpers ----------------
__device__ __forceinline__ float ex2f(float x) {
    float y; asm("ex2.approx.f32 %0, %1;" : "=f"(y) : "f"(x)); return y;
}
__device__ __forceinline__ uint32_t pack_f16(float lo, float hi) {
    uint32_t r; asm("cvt.rn.f16x2.f32 %0, %1, %2;" : "=r"(r) : "f"(hi), "f"(lo));
    return r;
}
__device__ __forceinline__ void mma_f16(float c[4], const uint32_t a[4],
                                        const uint32_t b[2]) {
    asm volatile(
        "mma.sync.aligned.m16n8k16.row.col.f32.f16.f16.f32 "
        "{%0,%1,%2,%3}, {%4,%5,%6,%7}, {%8,%9}, {%0,%1,%2,%3};\n"
        : "+f"(c[0]), "+f"(c[1]), "+f"(c[2]), "+f"(c[3])
        : "r"(a[0]), "r"(a[1]), "r"(a[2]), "r"(a[3]), "r"(b[0]), "r"(b[1]));
}
__device__ __forceinline__ void ldsm_x4(uint32_t& r0, uint32_t& r1,
                                        uint32_t& r2, uint32_t& r3,
                                        uint32_t addr) {
    asm volatile("ldmatrix.sync.aligned.m8n8.x4.shared.b16 {%0,%1,%2,%3}, [%4];\n"
                 : "=r"(r0), "=r"(r1), "=r"(r2), "=r"(r3) : "r"(addr));
}
__device__ __forceinline__ void ldsm_x4_t(uint32_t& r0, uint32_t& r1,
                                          uint32_t& r2, uint32_t& r3,
                                          uint32_t addr) {
    asm volatile("ldmatrix.sync.aligned.m8n8.x4.trans.shared.b16 {%0,%1,%2,%3}, [%4];\n"
                 : "=r"(r0), "=r"(r1), "=r"(r2), "=r"(r3) : "r"(addr));
}
__device__ __forceinline__ uint32_t smem_u32(const void* p) {
    return (uint32_t)__cvta_generic_to_shared(p);
}
__device__ __forceinline__ void cp16(uint32_t dst, const void* src) {
    asm volatile("cp.async.cg.shared.global [%0], [%1], 16;\n"
                 :: "r"(dst), "l"(src));
}
__device__ __forceinline__ void cp16z(uint32_t dst, const void* src, int srcsz) {
    asm volatile("cp.async.cg.shared.global [%0], [%1], 16, %2;\n"
                 :: "r"(dst), "l"(src), "r"(srcsz));
}
__device__ __forceinline__ void cp_commit() {
    asm volatile("cp.async.commit_group;\n");
}
template<int N> __device__ __forceinline__ void cp_wait() {
    asm volatile("cp.async.wait_group %0;\n" :: "n"(N));
}

// ---------------------------------------------------------------------------
// fused f32 -> f16 convert for all 4 tensors (8 elems/thread)
// ---------------------------------------------------------------------------
__global__ __launch_bounds__(256)
void f2h4(const float* __restrict__ s0, __half* __restrict__ d0, int n0,
          const float* __restrict__ s1, __half* __restrict__ d1, int n1,
          const float* __restrict__ s2, __half* __restrict__ d2, int n2,
          const float* __restrict__ s3, __half* __restrict__ d3, int n3) {
    int i = blockIdx.x * 256 + threadIdx.x;
    const float* s; __half* d; int j = i;
    if (j < n0)                { s = s0; d = d0; }
    else if ((j -= n0) < n1)   { s = s1; d = d1; }
    else if ((j -= n1) < n2)   { s = s2; d = d2; }
    else if ((j -= n2) < n3)   { s = s3; d = d3; }
    else return;
    float4 a = ((const float4*)s)[2 * j];
    float4 b = ((const float4*)s)[2 * j + 1];
    uint4 o;
    o.x = pack_f16(a.x, a.y); o.y = pack_f16(a.z, a.w);
    o.z = pack_f16(b.x, b.y); o.w = pack_f16(b.z, b.w);
    ((uint4*)d)[j] = o;
}

// ---------------------------------------------------------------------------
// FP16 NT GEMM: C = A @ B^T + bias  (A,B fp16; accum f32)
// 128x128x64 tile, 128 threads (4 warps), warp tile 64x64,
// 3-stage cp.async ring, LDSM fragments. Rows padded to 72 halves.
// ---------------------------------------------------------------------------
#define GSTGH (128 * 72)                 // halves per stage per matrix
#define GH_SMEM (3 * 2 * GSTGH * 2)      // 110592 B

template<bool WINDOW>
__global__ __launch_bounds__(128, 2)
void gemm_f16(const __half* __restrict__ A, const __half* __restrict__ B,
              const float* __restrict__ bias,
              float* __restrict__ Cf, __half* __restrict__ Ch,
              int M, int N, int K) {
    extern __shared__ __half smh[];
    __half* As = smh;                 // [3][128][72]
    __half* Bs = smh + 3 * GSTGH;     // [3][128][72]

    int tid = threadIdx.x;
    int bm = blockIdx.y * 128, bn = blockIdx.x * 128;
    int warp = tid >> 5, lane = tid & 31, gid = lane >> 2, tig = lane & 3;
    int l7 = lane & 7, l3 = lane >> 3;
    int wm = (warp >> 1) * 64, wn = (warp & 1) * 64;

    float acc[4][8][4];
#pragma unroll
    for (int i = 0; i < 4; i++)
#pragma unroll
        for (int j = 0; j < 8; j++)
#pragma unroll
            for (int c = 0; c < 4; c++) acc[i][j][c] = 0.f;

    auto load_stage = [&](int st, int k0) {
#pragma unroll
        for (int p = 0; p < 8; p++) {
            int id  = tid + p * 128;        // 0..1023
            int row = id >> 3;              // 0..127
            int kq  = (id & 7) << 3;        // 0..56 halves
            uint32_t da = smem_u32(&As[st * GSTGH + row * 72 + kq]);
            if (WINDOW) {
                int m = bm + row;
                int bidx = m >> 11, s = m & (CS - 1);
                int f = k0 + kq, kk = f >> 10, j = f & (CD - 1);
                const __half* src = A + (((size_t)bidx * CS + s + kk) << 10) + j;
                cp16z(da, src, (s + kk < CS) ? 16 : 0);
            } else {
                cp16(da, A + (size_t)(bm + row) * K + k0 + kq);
            }
            cp16(smem_u32(&Bs[st * GSTGH + row * 72 + kq]),
                 B + (size_t)(bn + row) * K + k0 + kq);
        }
        cp_commit();
    };

    int nk = K >> 6;   // BK=64
    load_stage(0, 0);
    load_stage(1, 64);

    int st = 0, pfst = 2;
    for (int kc = 0; kc < nk; kc++) {
        cp_wait<1>();
        __syncthreads();

        int pf = kc + 2;
        if (pf < nk) load_stage(pfst, pf << 6);
        else cp_commit();

        uint32_t Abase = smem_u32(As + st * GSTGH);
        uint32_t Bbase = smem_u32(Bs + st * GSTGH);
#pragma unroll
        for (int g = 0; g < 64; g += 16) {
            uint32_t a[4][4], bf[8][2];
#pragma unroll
            for (int ti = 0; ti < 4; ti++) {
                uint32_t adr = Abase +
                    ((wm + ti * 16 + (l3 & 1) * 8 + l7) * 72 +
                     g + (l3 >> 1) * 8) * 2;
                ldsm_x4(a[ti][0], a[ti][1], a[ti][2], a[ti][3], adr);
            }
#pragma unroll
            for (int tp = 0; tp < 4; tp++) {
                uint32_t adr = Bbase +
                    ((wn + tp * 16 + (l3 & 1) * 8 + l7) * 72 +
                     g + (l3 >> 1) * 8) * 2;
                uint32_t r0, r1, r2, r3;
                ldsm_x4(r0, r1, r2, r3, adr);
                bf[2 * tp][0] = r0; bf[2 * tp][1] = r2;
                bf[2 * tp + 1][0] = r1; bf[2 * tp + 1][1] = r3;
            }
#pragma unroll
            for (int ti = 0; ti < 4; ti++)
#pragma unroll
                for (int tj = 0; tj < 8; tj++)
                    mma_f16(acc[ti][tj], a[ti], bf[tj]);
        }

        st   = (st   == 2) ? 0 : st + 1;
        pfst = (pfst == 2) ? 0 : pfst + 1;
    }

#pragma unroll
    for (int ti = 0; ti < 4; ti++) {
#pragma unroll
        for (int hh = 0; hh < 2; hh++) {
            int row = bm + wm + ti * 16 + gid + 8 * hh;
#pragma unroll
            for (int tj = 0; tj < 8; tj++) {
                int col = bn + wn + tj * 8 + 2 * tig;
                float ox = acc[ti][tj][2 * hh + 0] + bias[col + 0];
                float oy = acc[ti][tj][2 * hh + 1] + bias[col + 1];
                if (Cf) *(float2*)&Cf[(size_t)row * N + col] = make_float2(ox, oy);
                if (Ch) *(uint32_t*)&Ch[(size_t)row * N + col] = pack_f16(ox, oy);
            }
        }
    }
}

// ---------------------------------------------------------------------------
// FP16 flash attention (unchanged from R12). 8 warps x 16 q-rows, 2 CTAs/SM.
// kv tiles of 128 (two 64-row halves), 2-stage ring.
// ---------------------------------------------------------------------------
#define FKV (128 * 72)                      // halves per stage per matrix
#define FA_SMEM (2 * 2 * FKV * 2)           // 73728 B

__global__ __launch_bounds__(256, 2)
void flash_f16(const __half* __restrict__ qkv, __half* __restrict__ out) {
    extern __shared__ __half smh[];
    __half* Ks = smh;                 // [2][128][72]
    __half* Vs = smh + 2 * FKV;       // [2][128][72]

    int b = blockIdx.y >> 4, h = blockIdx.y & 15;
    int q0 = blockIdx.x << 7;
    int tid = threadIdx.x, warp = tid >> 5, lane = tid & 31;
    int gid = lane >> 2, tig = lane & 3;
    int wq = warp * 16;
    int l7 = lane & 7, l3 = lane >> 3;

    const size_t rstr = 3 * CD;
    const __half* qb = qkv + (size_t)b * CS * rstr + h * CDH;
    const __half* kb = qb + CD;
    const __half* vb = qb + 2 * CD;
    const float qscale = 1.4426950408889634f * 0.125f;   // log2e / sqrt(dh)

    // ---- stage Q through kv-stage 0 (128*72 fits exactly)
#pragma unroll
    for (int p = 0; p < 4; p++) {
        int id  = tid + p * 256;        // 0..1023
        int row = id >> 3;              // 0..127
        int c8  = (id & 7) << 3;        // 0..56
        cp16(smem_u32(&Ks[row * 72 + c8]),
             qb + (size_t)(q0 + row) * rstr + c8);
    }
    cp_commit();
    cp_wait<0>();
    __syncthreads();

    uint32_t Qbase = smem_u32(Ks);
    uint32_t qf[4][4];
#pragma unroll
    for (int g4 = 0; g4 < 4; g4++) {
        uint32_t adr = Qbase +
            ((wq + (l3 & 1) * 8 + l7) * 72 + g4 * 16 + (l3 >> 1) * 8) * 2;
        ldsm_x4(qf[g4][0], qf[g4][1], qf[g4][2], qf[g4][3], adr);
    }
    __syncthreads();

    auto load_kv = [&](int st, int kt) {
#pragma unroll
        for (int p = 0; p < 4; p++) {
            int id  = tid + p * 256;    // 0..1023
            int row = id >> 3;          // 0..127
            int c8  = (id & 7) << 3;
            cp16(smem_u32(&Ks[st * FKV + row * 72 + c8]),
                 kb + (size_t)(kt + row) * rstr + c8);
            cp16(smem_u32(&Vs[st * FKV + row * 72 + c8]),
                 vb + (size_t)(kt + row) * rstr + c8);
        }
        cp_commit();
    };

    load_kv(0, 0);
    load_kv(1, 128);

    float o[9][4];
#pragma unroll
    for (int n = 0; n < 9; n++)
#pragma unroll
        for (int c = 0; c < 4; c++) o[n][c] = 0.f;

    const uint32_t bones = (gid == 0) ? 0x3C003C00u : 0u;   // fp16 {1,1}
    const int nkt = CS / 128;   // 16

    for (int it = 0; it < nkt; it++) {
        int st = it & 1;
        cp_wait<1>();
        __syncthreads();

#pragma unroll
        for (int half = 0; half < 2; half++) {
            uint32_t Kbase = smem_u32(Ks + st * FKV + half * 64 * 72);
            uint32_t Vbase = smem_u32(Vs + st * FKV + half * 64 * 72);

            float sc[8][4];
#pragma unroll
            for (int n = 0; n < 8; n++)
#pragma unroll
                for (int c = 0; c < 4; c++) sc[n][c] = 0.f;
#pragma unroll
            for (int g4 = 0; g4 < 4; g4++) {
#pragma unroll
                for (int np = 0; np < 4; np++) {
                    uint32_t adr = Kbase +
                        ((np * 16 + (l3 & 1) * 8 + l7) * 72 +
                         g4 * 16 + (l3 >> 1) * 8) * 2;
                    uint32_t r0, r1, r2, r3;
                    ldsm_x4(r0, r1, r2, r3, adr);
                    uint32_t b0[2] = {r0, r2};
                    uint32_t b1[2] = {r1, r3};
                    mma_f16(sc[2 * np],     qf[g4], b0);
                    mma_f16(sc[2 * np + 1], qf[g4], b1);
                }
            }

            uint32_t pf[4][4];
#pragma unroll
            for (int n = 0; n < 8; n++) {
                int t = n >> 1, hi = (n & 1) << 1;
                pf[t][hi + 0] = pack_f16(ex2f(sc[n][0] * qscale),
                                         ex2f(sc[n][1] * qscale));
                pf[t][hi + 1] = pack_f16(ex2f(sc[n][2] * qscale),
                                         ex2f(sc[n][3] * qscale));
            }

#pragma unroll
            for (int t = 0; t < 4; t++) {
#pragma unroll
                for (int a = 0; a < 4; a++) {
                    uint32_t adr = Vbase +
                        (16 * t + (l3 & 1) * 8 + l7) * 144 +
                        (2 * a + (l3 >> 1)) * 16;
                    uint32_t v0, v1, v2, v3;
                    ldsm_x4_t(v0, v1, v2, v3, adr);
                    uint32_t bv0[2] = {v0, v1};
                    uint32_t bv1[2] = {v2, v3};
                    mma_f16(o[2 * a],     pf[t], bv0);
                    mma_f16(o[2 * a + 1], pf[t], bv1);
                }
                {
                    uint32_t bv[2] = {bones, bones};
                    mma_f16(o[8], pf[t], bv);
                }
            }
        }

        __syncthreads();
        if (it + 2 < nkt) load_kv(st, (it + 2) * 128);
        else cp_commit();
    }

    int base = lane & 28;
#pragma unroll
    for (int hh = 0; hh < 2; hh++) {
        float lsv = __shfl_sync(0xffffffffu, o[8][hh ? 2 : 0], base);
        float inv = 1.f / lsv;
        int row = q0 + wq + gid + 8 * hh;
#pragma unroll
        for (int n = 0; n < 8; n++) {
            int col = h * CDH + n * 8 + 2 * tig;
            *(uint32_t*)&out[((size_t)b * CS + row) * CD + col] =
                pack_f16(o[n][2 * hh] * inv, o[n][2 * hh + 1] * inv);
        }
    }
}

// ---------------------------------------------------------------------------
// Fused residual add + LayerNorm
// ---------------------------------------------------------------------------
__global__ __launch_bounds__(256)
void add_ln(const float* __restrict__ chunk, const float* __restrict__ proj,
            const float* __restrict__ g, const float* __restrict__ beta,
            float* __restrict__ out) {
    int row = blockIdx.x;
    int tid = threadIdx.x;
    size_t base = (size_t)row * CD + tid * 4;

    float4 c = *(const float4*)&chunk[base];
    float4 p = *(const float4*)&proj[base];
    float4 x = make_float4(c.x + p.x, c.y + p.y, c.z + p.z, c.w + p.w);

    float s  = x.x + x.y + x.z + x.w;
    float s2 = x.x * x.x + x.y * x.y + x.z * x.z + x.w * x.w;
#pragma unroll
    for (int off = 16; off; off >>= 1) {
        s  += __shfl_xor_sync(0xffffffffu, s,  off);
        s2 += __shfl_xor_sync(0xffffffffu, s2, off);
    }
    __shared__ float rs[8], rs2[8];
    __shared__ float s_mu, s_rstd;
    int lane = tid & 31, warp = tid >> 5;
    if (lane == 0) { rs[warp] = s; rs2[warp] = s2; }
    __syncthreads();
    if (tid == 0) {
        float a = 0.f, b2 = 0.f;
#pragma unroll
        for (int w = 0; w < 8; w++) { a += rs[w]; b2 += rs2[w]; }
        float mean = a * (1.f / CD);
        float var  = b2 * (1.f / CD) - mean * mean;
        s_mu = mean;
        s_rstd = rsqrtf(var + LN_EPS);
    }
    __syncthreads();
    float mu = s_mu, rstd = s_rstd;

    float4 gv = *(const float4*)&g[tid * 4];
    float4 bv = *(const float4*)&beta[tid * 4];
    float4 y;
    y.x = (x.x - mu) * rstd * gv.x + bv.x;
    y.y = (x.y - mu) * rstd * gv.y + bv.y;
    y.z = (x.z - mu) * rstd * gv.z + bv.z;
    y.w = (x.w - mu) * rstd * gv.w + bv.w;
    *(float4*)&out[base] = y;
}

// ---------------------------------------------------------------------------
extern "C" void kernel_launch(void* const* d_in, const int* in_sizes, int n_in,
                              void* d_out, int out_size) {
    const float* emb     = (const float*)d_in[0];
    const float* chunk_w = (const float*)d_in[1];
    const float* chunk_b = (const float*)d_in[2];
    const float* in_w    = (const float*)d_in[3];
    const float* in_b    = (const float*)d_in[4];
    const float* out_w   = (const float*)d_in[5];
    const float* out_b   = (const float*)d_in[6];
    const float* ln_g    = (const float*)d_in[7];
    const float* ln_b    = (const float*)d_in[8];
    float* out = (float*)d_out;

    float *chunk, *proj;
    __half *emb_h, *chunk_h, *qkv_h, *attn_h, *cw_h, *iw_h, *ow_h;
    cudaGetSymbolAddress((void**)&chunk,   g_chunk);
    cudaGetSymbolAddress((void**)&proj,    g_proj);
    cudaGetSymbolAddress((void**)&emb_h,   g_emb_h);
    cudaGetSymbolAddress((void**)&chunk_h, g_chunk_h);
    cudaGetSymbolAddress((void**)&qkv_h,   g_qkv_h);
    cudaGetSymbolAddress((void**)&attn_h,  g_attn_h);
    cudaGetSymbolAddress((void**)&cw_h,    g_cw_h);
    cudaGetSymbolAddress((void**)&iw_h,    g_iw_h);
    cudaGetSymbolAddress((void**)&ow_h,    g_ow_h);

    cudaFuncSetAttribute(gemm_f16<true>,
                         cudaFuncAttributeMaxDynamicSharedMemorySize, GH_SMEM);
    cudaFuncSetAttribute(gemm_f16<false>,
                         cudaFuncAttributeMaxDynamicSharedMemorySize, GH_SMEM);
    cudaFuncSetAttribute(flash_f16,
                         cudaFuncAttributeMaxDynamicSharedMemorySize, FA_SMEM);

    // 0) fused f32 -> f16 conversions
    {
        int n0 = MROWS * CD / 8;
        int n1 = CD * 2 * CD / 8;
        int n2 = 3 * CD * CD / 8;
        int n3 = CD * CD / 8;
        int nt = n0 + n1 + n2 + n3;
        f2h4<<<(nt + 255) / 256, 256>>>(emb, emb_h, n0, chunk_w, cw_h, n1,
                                        in_w, iw_h, n2, out_w, ow_h, n3);
    }
    // 1) chunk = windows @ chunk_w^T + chunk_b  (f32 + f16 outputs)
    {
        dim3 grid(CD / 128, MROWS / 128);
        gemm_f16<true><<<grid, 128, GH_SMEM>>>(emb_h, cw_h, chunk_b,
                                               chunk, chunk_h,
                                               MROWS, CD, 2 * CD);
    }
    // 2) qkv = chunk @ in_proj_w^T + in_proj_b  (f16 output only)
    {
        dim3 grid(3 * CD / 128, MROWS / 128);
        gemm_f16<false><<<grid, 128, GH_SMEM>>>(chunk_h, iw_h, in_b,
                                                nullptr, qkv_h,
                                                MROWS, 3 * CD, CD);
    }
    // 3) flash attention (fp16 in/out)
    {
        dim3 grid(CS / 128, CB * CH);
        flash_f16<<<grid, 256, FA_SMEM>>>(qkv_h, attn_h);
    }
    // 4) proj = attn @ out_proj_w^T + out_proj_b  (f32 output only)
    {
        dim3 grid(CD / 128, MROWS / 128);
        gemm_f16<false><<<grid, 128, GH_SMEM>>>(attn_h, ow_h, out_b,
                                                proj, nullptr,
                                                MROWS, CD, CD);
    }
    // 5) out = LayerNorm(chunk + proj)
    add_ln<<<MROWS, 256>>>(chunk, proj, ln_g, ln_b, out);
}